// round 13
// baseline (speedup 1.0000x reference)
#include <cuda_runtime.h>
#include <cuda_bf16.h>

#define NBATCH 32
#define NSUP   100
#define NWAY   10
#define NZV    1000
#define NQRY   150

// ---------------- device scratch ----------------
__device__ float g_krn   [NBATCH * NSUP * NSUP];          // sup sup^T (bitwise symmetric)
__device__ float g_compat[NBATCH * NSUP * NQRY];
__device__ float g_Hinv  [NBATCH * NWAY * NSUP * NSUP];   // stored[col*100+row] (symmetric)
__device__ float g_t     [NBATCH * NWAY * NSUP];
// all NZV-state arrays use i2 = c*100 + ss layout
__device__ float g_z  [NBATCH * NZV];
__device__ float g_s  [NBATCH * NZV];
__device__ float g_lam[NBATCH * NZV];
__device__ float g_gz [NBATCH * NZV];
__device__ float g_rp [NBATCH * NZV];
__device__ float g_rc [NBATCH * NZV];
__device__ float g_r1 [NBATCH * NZV];
__device__ float g_d  [NBATCH * NZV];
__device__ float g_nu [NBATCH * NSUP];
__device__ float g_rp2[NBATCH * NSUP];

// ---------------- gram: kernel (100x100) + compat (100x150) ----------------
__global__ void __launch_bounds__(400) k_gram(const float* __restrict__ sup,
                                              const float* __restrict__ qry) {
    int b  = blockIdx.x;
    int c0 = blockIdx.y * 64;
    __shared__ __align__(16) float As[32 * 100];
    __shared__ __align__(16) float Bs[32 * 64];
    int tid = threadIdx.x;
    int tx = tid & 15;
    int ty = tid >> 4;
    float acc[4][4];
#pragma unroll
    for (int u = 0; u < 4; u++)
#pragma unroll
        for (int v = 0; v < 4; v++) acc[u][v] = 0.f;

    const float* supb = sup + (size_t)b * NSUP * 512;
    const float* qryb = qry + (size_t)b * NQRY * 512;

    for (int kt = 0; kt < 512; kt += 32) {
        __syncthreads();
        for (int e = tid; e < NSUP * 32; e += 400) {
            int r = e >> 5, kk = e & 31;
            As[kk * 100 + r] = supb[r * 512 + kt + kk];
        }
        for (int e = tid; e < 64 * 32; e += 400) {
            int cc = e >> 5, kk = e & 31;
            int col = c0 + cc;
            float v = 0.f;
            if (col < NSUP)      v = supb[col * 512 + kt + kk];
            else if (col < 250)  v = qryb[(col - NSUP) * 512 + kt + kk];
            Bs[kk * 64 + cc] = v;
        }
        __syncthreads();
#pragma unroll
        for (int kk = 0; kk < 32; kk++) {
            float4 a  = *(const float4*)(As + kk * 100 + 4 * ty);
            float4 bb = *(const float4*)(Bs + kk * 64 + 4 * tx);
            acc[0][0] = fmaf(a.x, bb.x, acc[0][0]); acc[0][1] = fmaf(a.x, bb.y, acc[0][1]);
            acc[0][2] = fmaf(a.x, bb.z, acc[0][2]); acc[0][3] = fmaf(a.x, bb.w, acc[0][3]);
            acc[1][0] = fmaf(a.y, bb.x, acc[1][0]); acc[1][1] = fmaf(a.y, bb.y, acc[1][1]);
            acc[1][2] = fmaf(a.y, bb.z, acc[1][2]); acc[1][3] = fmaf(a.y, bb.w, acc[1][3]);
            acc[2][0] = fmaf(a.z, bb.x, acc[2][0]); acc[2][1] = fmaf(a.z, bb.y, acc[2][1]);
            acc[2][2] = fmaf(a.z, bb.z, acc[2][2]); acc[2][3] = fmaf(a.z, bb.w, acc[2][3]);
            acc[3][0] = fmaf(a.w, bb.x, acc[3][0]); acc[3][1] = fmaf(a.w, bb.y, acc[3][1]);
            acc[3][2] = fmaf(a.w, bb.z, acc[3][2]); acc[3][3] = fmaf(a.w, bb.w, acc[3][3]);
        }
    }
#pragma unroll
    for (int u = 0; u < 4; u++) {
        int r = 4 * ty + u;
#pragma unroll
        for (int v = 0; v < 4; v++) {
            int col = c0 + 4 * tx + v;
            if (col < NSUP)
                g_krn[b * NSUP * NSUP + r * NSUP + col] = acc[u][v];
            else if (col < 250)
                g_compat[b * NSUP * NQRY + r * NQRY + (col - NSUP)] = acc[u][v];
        }
    }
}

// ---------------- init (i2 layout) ----------------
__global__ void __launch_bounds__(256) k_init(const int* __restrict__ lab) {
    int b = blockIdx.x, tid = threadIdx.x;
    for (int i = tid; i < NZV; i += 256) {
        int gi = b * NZV + i;
        int ss = i % NSUP, c = i / NSUP;
        float y = (lab[b * NSUP + ss] == c) ? 1.f : 0.f;
        g_z[gi] = 0.f; g_s[gi] = 1.f; g_lam[gi] = 1.f; g_gz[gi] = 0.f;
        float rd = 1.f - y;
        float rp = 1.f - 0.1f * y;
        float rc = 0.9f;
        g_rp[gi] = rp;
        g_rc[gi] = rc;
        g_d [gi] = 1.f;
        g_r1[gi] = -rd + (rc - rp);
    }
    for (int ss = tid; ss < NSUP; ss += 256) {
        g_nu [b * NSUP + ss] = 0.f;
        g_rp2[b * NSUP + ss] = 0.f;
    }
}

// ---------------- rank-1 sweep row update (16 cols, pivot chunk in p[4]) ----------------
__device__ __forceinline__ void upd_row(float* Am, int rm, int k, int base,
                                        float sr, float invp, const float4* p) {
    if (rm == k) {
#pragma unroll
        for (int g = 0; g < 4; g++)
#pragma unroll
            for (int cp = 0; cp < 4; cp++) {
                int jj = 4 * g + cp;
                float sv = Am[jj] * invp;
                Am[jj] = (base + jj == k) ? invp : sv;
            }
    } else {
        float tm = (rm < k) ? -sr * invp : sr * invp;
#pragma unroll
        for (int g = 0; g < 4; g++) {
#pragma unroll
            for (int cp = 0; cp < 4; cp++) {
                int jj = 4 * g + cp;
                float pj = ((const float*)&p[g])[cp];
                float u = fmaf(-tm, pj, Am[jj]);
                Am[jj] = (base + jj == k) ? -tm : u;
            }
        }
    }
}

// ---------------- shared sweep loop (2 rows x 16 cols per thread) ----------------
// srow double-buffered 112-wide pivot row; cols 0..99 matrix, 100 rhs, 101..111 pad.
__device__ __forceinline__ void sweep2x16(float A0[16], float A1[16],
                                          float srow[2][112],
                                          int t, int rp, int base,
                                          int r0, int r1) {
    for (int k = 0; k < NSUP; k++) {
        int buf = k & 1;
        if (t < 350) {
            const float* row = srow[buf];
            float invp = __fdividef(1.0f, row[k]);
            float sr0 = row[r0];
            float sr1 = row[r1];
            float4 p[4];
            p[0] = *(const float4*)(row + base);
            p[1] = *(const float4*)(row + base + 4);
            p[2] = *(const float4*)(row + base + 8);
            p[3] = *(const float4*)(row + base + 12);
            upd_row(A0, r0, k, base, sr0, invp, p);
            upd_row(A1, r1, k, base, sr1, invp, p);
            int kn = k + 1;
            if (kn < NSUP && rp == (kn % 50)) {
                const float* Am = (kn < 50) ? A0 : A1;
                float4* dst = (float4*)(srow[buf ^ 1] + base);
                dst[0] = make_float4(Am[0],  Am[1],  Am[2],  Am[3]);
                dst[1] = make_float4(Am[4],  Am[5],  Am[6],  Am[7]);
                dst[2] = make_float4(Am[8],  Am[9],  Am[10], Am[11]);
                dst[3] = make_float4(Am[12], Am[13], Am[14], Am[15]);
            }
        }
        __syncthreads();
    }
}

// ---------------- per-class inversion (grid=320, block=352, 2 blocks/SM) ----------------
__global__ void __launch_bounds__(352, 2) k_invert() {
    int bc = blockIdx.x;
    int b = bc / NWAY, c = bc - b * NWAY;
    int t = threadIdx.x;
    int chunk = t / 50, rp = t - chunk * 50;
    int base = chunk * 16;
    int r0 = rp, r1 = rp + 50;
    float A0[16], A1[16];
    __shared__ __align__(16) float srow[2][112];

    if (t < 350) {
        const float* K = g_krn + (size_t)b * NSUP * NSUP;
        float d0 = 1.0f + g_d[b * NZV + c * NSUP + r0];
        float d1 = 1.0f + g_d[b * NZV + c * NSUP + r1];
        float r1v0 = g_r1[b * NZV + c * NSUP + r0];
        float r1v1 = g_r1[b * NZV + c * NSUP + r1];
#pragma unroll
        for (int jj = 0; jj < 16; jj++) {
            int col = base + jj;
            float v0 = 0.f, v1 = 0.f;
            if (col < NSUP) {
                v0 = K[col * NSUP + r0];      // coalesced (symmetric)
                v1 = K[col * NSUP + r1];
                if (col == r0) v0 += d0;
                if (col == r1) v1 += d1;
            } else if (col == NSUP) {
                v0 = r1v0; v1 = r1v1;
            }
            A0[jj] = v0; A1[jj] = v1;
        }
        if (rp == 0) {   // stage pivot row 0 (row r0 == 0)
            float4* dst = (float4*)(srow[0] + base);
            dst[0] = make_float4(A0[0],  A0[1],  A0[2],  A0[3]);
            dst[1] = make_float4(A0[4],  A0[5],  A0[6],  A0[7]);
            dst[2] = make_float4(A0[8],  A0[9],  A0[10], A0[11]);
            dst[3] = make_float4(A0[12], A0[13], A0[14], A0[15]);
        }
    }
    __syncthreads();

    sweep2x16(A0, A1, srow, t, rp, base, r0, r1);

    if (t < 350) {
        float* Ho = g_Hinv + (size_t)bc * (NSUP * NSUP);
#pragma unroll
        for (int jj = 0; jj < 16; jj++) {
            int col = base + jj;
            if (col < NSUP) {                // stored[col*100+row], coalesced
                Ho[col * NSUP + r0] = A0[jj];
                Ho[col * NSUP + r1] = A1[jj];
            }
        }
        if (chunk == 6) {                    // col 100 = rhs -> t
            g_t[bc * NSUP + r0] = A0[4];
            g_t[bc * NSUP + r1] = A1[4];
        }
    }
}

// ---------------- Schur solve + step + residuals (grid=32, block=352) ----------------
__global__ void __launch_bounds__(352) k_schur(const int* __restrict__ lab) {
    int b = blockIdx.x;
    int t = threadIdx.x, lane = t & 31, w = t >> 5;
    int chunk = t / 50, rp = t - chunk * 50;
    int base = chunk * 16;
    int r0 = rp, r1 = rp + 50;
    float A0[16], A1[16];
    __shared__ __align__(16) float srow[2][112];
    __shared__ __align__(16) float s_dnu[NSUP];
    __shared__ float s_dz[NZV];
    __shared__ float red[11];
    __shared__ float s_res[2];

    const float* Hb = g_Hinv + (size_t)b * NWAY * NSUP * NSUP;

    // Phase A: S = sum_c Hinv_c ; border col = rhs
    if (t < 350) {
#pragma unroll
        for (int jj = 0; jj < 16; jj++) {
            int col = base + jj;
            float v0 = 0.f, v1 = 0.f;
            if (col < NSUP) {
#pragma unroll
                for (int c = 0; c < NWAY; c++) {
                    const float* Hc = Hb + (size_t)c * (NSUP * NSUP) + col * NSUP;
                    v0 += Hc[r0];
                    v1 += Hc[r1];
                }
            } else if (col == NSUP) {
                v0 = g_rp2[b * NSUP + r0];
                v1 = g_rp2[b * NSUP + r1];
#pragma unroll
                for (int c = 0; c < NWAY; c++) {
                    v0 += g_t[(b * NWAY + c) * NSUP + r0];
                    v1 += g_t[(b * NWAY + c) * NSUP + r1];
                }
            }
            A0[jj] = v0; A1[jj] = v1;
        }
        if (rp == 0) {
            float4* dst = (float4*)(srow[0] + base);
            dst[0] = make_float4(A0[0],  A0[1],  A0[2],  A0[3]);
            dst[1] = make_float4(A0[4],  A0[5],  A0[6],  A0[7]);
            dst[2] = make_float4(A0[8],  A0[9],  A0[10], A0[11]);
            dst[3] = make_float4(A0[12], A0[13], A0[14], A0[15]);
        }
    }
    __syncthreads();

    sweep2x16(A0, A1, srow, t, rp, base, r0, r1);

    if (t < 350 && chunk == 6) {
        s_dnu[r0] = A0[4];
        s_dnu[r1] = A1[4];
    }
    __syncthreads();

    // Phase D: dz (warp per i2 row; float4 over 25 lanes, coalesced)
    for (int ri = w; ri < NZV; ri += 11) {
        int c = ri / NSUP, ss = ri - c * NSUP;
        const float* Hrow = Hb + (size_t)c * (NSUP * NSUP) + ss * NSUP;
        float acc = 0.f;
        if (lane < 25) {
            float4 hv = *(const float4*)(Hrow + 4 * lane);
            float4 dv = *(const float4*)(&s_dnu[4 * lane]);
            acc = hv.x * dv.x + hv.y * dv.y + hv.z * dv.z + hv.w * dv.w;
        }
#pragma unroll
        for (int off = 16; off; off >>= 1) acc += __shfl_xor_sync(0xffffffffu, acc, off);
        if (lane == 0) s_dz[ri] = g_t[(b * NWAY + c) * NSUP + ss] - acc;
    }
    __syncthreads();

    // Phase E: steps, alpha, state update, residuals (i2 layout; 3 elems/thread)
    const float FINF = __int_as_float(0x7f800000);
    float dzv[3], dsv[3], dlv[3], sv[3], lv[3], zv[3], gzv[3];
    float amin = FINF;
#pragma unroll
    for (int q = 0; q < 3; q++) {
        int i = t + q * 352;
        if (i < NZV) {
            int gi = b * NZV + i;
            float dz = s_dz[i];
            float s0 = g_s[gi], l0 = g_lam[gi];
            float ds = -g_rp[gi] - dz;
            float dl = (-g_rc[gi] - l0 * ds) / s0;
            dzv[q] = dz; dsv[q] = ds; dlv[q] = dl; sv[q] = s0; lv[q] = l0;
            if (ds < 0.f) amin = fminf(amin, -s0 / ds);
            if (dl < 0.f) amin = fminf(amin, -l0 / dl);
        }
    }
#pragma unroll
    for (int off = 16; off; off >>= 1) amin = fminf(amin, __shfl_xor_sync(0xffffffffu, amin, off));
    if (lane == 0) red[w] = amin;
    __syncthreads();
    if (w == 0) {
        float v = (lane < 11) ? red[lane] : FINF;
#pragma unroll
        for (int off = 8; off; off >>= 1) v = fminf(v, __shfl_xor_sync(0xffffffffu, v, off));
        if (lane == 0) s_res[0] = fminf(1.0f, 0.99f * v);
    }
    __syncthreads();
    float alpha = s_res[0];

    float muloc = 0.f;
#pragma unroll
    for (int q = 0; q < 3; q++) {
        int i = t + q * 352;
        if (i < NZV) {
            int gi = b * NZV + i;
            int ss = i % NSUP;
            float zn = g_z[gi] + alpha * dzv[q]; g_z[gi] = zn; zv[q] = zn;
            float sn = sv[q] + alpha * dsv[q];   g_s[gi] = sn; sv[q] = sn;
            float ln = lv[q] + alpha * dlv[q];   g_lam[gi] = ln; lv[q] = ln;
            float gdz = g_r1[gi] - s_dnu[ss] - g_d[gi] * dzv[q];   // (G dz)_i exactly
            float gzn = g_gz[gi] + alpha * gdz;  g_gz[gi] = gzn; gzv[q] = gzn;
            muloc += sn * ln;
            s_dz[i] = zn;   // reuse as z_new
        }
    }
#pragma unroll
    for (int off = 16; off; off >>= 1) muloc += __shfl_xor_sync(0xffffffffu, muloc, off);
    if (lane == 0) red[w] = muloc;
    __syncthreads();
    if (w == 0) {
        float v = (lane < 11) ? red[lane] : 0.f;
#pragma unroll
        for (int off = 8; off; off >>= 1) v += __shfl_xor_sync(0xffffffffu, v, off);
        if (lane == 0) s_res[1] = v;
    }
    __syncthreads();
    float mu = s_res[1] * (1.0f / (float)NZV);

    // nu update (overwrite s_dnu with nu_new) + rp2
    if (t < NSUP) {
        float nn = g_nu[b * NSUP + t] + alpha * s_dnu[t];
        s_dnu[t] = nn;
        g_nu[b * NSUP + t] = nn;
        float acc = 0.f;
#pragma unroll
        for (int c = 0; c < NWAY; c++) acc += s_dz[c * NSUP + t];
        g_rp2[b * NSUP + t] = acc;
    }
    __syncthreads();

    // next-iteration residuals (elementwise; no matvec)
#pragma unroll
    for (int q = 0; q < 3; q++) {
        int i = t + q * 352;
        if (i < NZV) {
            int gi = b * NZV + i;
            int ss = i % NSUP, c = i / NSUP;
            float y = (lab[b * NSUP + ss] == c) ? 1.f : 0.f;
            float rd = gzv[q] - y + lv[q] + s_dnu[ss];
            float rp = zv[q] + sv[q] - 0.1f * y;
            float rc = lv[q] * sv[q] - 0.1f * mu;
            float invs = 1.0f / sv[q];
            g_rp[gi] = rp;
            g_rc[gi] = rc;
            g_d [gi] = lv[q] * invs;
            g_r1[gi] = -rd + (rc - lv[q] * rp) * invs;
        }
    }
}

// ---------------- logits epilogue ----------------
__global__ void __launch_bounds__(256) k_logits(float* __restrict__ out) {
    int b = blockIdx.x, tid = threadIdx.x;
    __shared__ float sh_z[NZV];
    for (int i = tid; i < NZV; i += 256) sh_z[i] = g_z[b * NZV + i];
    __syncthreads();
    const float* cb = &g_compat[b * NSUP * NQRY];
    for (int o = tid; o < NQRY * NWAY; o += 256) {
        int q = o / NWAY, n = o - q * NWAY;
        float acc = 0.f;
        for (int s = 0; s < NSUP; s++)
            acc = fmaf(cb[s * NQRY + q], sh_z[n * NSUP + s], acc);
        out[b * NQRY * NWAY + o] = acc;
    }
}

// ---------------- launcher ----------------
extern "C" void kernel_launch(void* const* d_in, const int* in_sizes, int n_in,
                              void* d_out, int out_size) {
    const float* sup = (const float*)d_in[0];
    const int*   lab = (const int*)  d_in[1];
    const float* qry = (const float*)d_in[2];
    float* out = (float*)d_out;

    k_gram<<<dim3(NBATCH, 4), 400>>>(sup, qry);
    k_init<<<NBATCH, 256>>>(lab);
    for (int it = 0; it < 15; ++it) {
        k_invert<<<NBATCH * NWAY, 352>>>();
        k_schur<<<NBATCH, 352>>>(lab);
    }
    k_logits<<<NBATCH, 256>>>(out);
}